// round 8
// baseline (speedup 1.0000x reference)
#include <cuda_runtime.h>
#include <math.h>
#include <stdint.h>

// Problem constants (fixed shapes from reference setup_inputs)
#define BB   16
#define NN1  1024
#define NN2  4096
#define CC1  256
#define CC2  128
#define CIN  384           // C1 + C2
#define HH   256           // H1 == H2
#define MM   (BB * NN2)    // 65536 rows through the MLP

// ---------------------------------------------------------------------------
// Scratch (device globals; no allocations allowed)
// ---------------------------------------------------------------------------
__device__ float g_f1t[(size_t)BB * NN1 * CC1];     // f1 transposed [B][N1][C1]
__device__ float g_X  [(size_t)MM * CIN];           // concat(new_feat, f2) [M][384]
__device__ float g_Y1 [(size_t)MM * HH];            // layer1 pre-BN output
__device__ float g_Y2 [(size_t)MM * HH];            // layer2 pre-BN output
__device__ float g_sum[4 * HH];                     // [sum1 | sq1 | sum2 | sq2]
__device__ float g_nrm[4 * HH];                     // [sc1 | sh1 | sc2 | sh2]

// ---------------------------------------------------------------------------
// f32x2 helpers (FFMA2: 2 FMAs per instruction on the fma pipe)
// ---------------------------------------------------------------------------
__device__ __forceinline__ void ffma2(unsigned long long& d,
                                      unsigned long long a,
                                      unsigned long long b) {
    asm("fma.rn.f32x2 %0, %1, %2, %0;" : "+l"(d) : "l"(a), "l"(b));
}
__device__ __forceinline__ unsigned long long pk2(float x) {
    unsigned long long r;
    unsigned int u = __float_as_uint(x);
    asm("mov.b64 %0, {%1, %1};" : "=l"(r) : "r"(u));
    return r;
}
__device__ __forceinline__ float2 upk2(unsigned long long v) {
    unsigned int lo, hi;
    asm("mov.b64 {%0, %1}, %2;" : "=r"(lo), "=r"(hi) : "l"(v));
    return make_float2(__uint_as_float(lo), __uint_as_float(hi));
}

// ---------------------------------------------------------------------------
// Kernel: zero the BN statistics accumulators (must be re-zeroed each replay)
// ---------------------------------------------------------------------------
__global__ void zero_stats_kernel() {
    for (int i = threadIdx.x; i < 4 * HH; i += blockDim.x) g_sum[i] = 0.f;
}

// ---------------------------------------------------------------------------
// Kernel: transpose features1 [B][C1][N1] -> g_f1t [B][N1][C1]
// grid (N1/32, C1/32, B), block (32, 8)
// ---------------------------------------------------------------------------
__global__ __launch_bounds__(256) void transpose_f1_kernel(const float* __restrict__ f1) {
    __shared__ float t[32][33];
    const int b  = blockIdx.z;
    const int n0 = blockIdx.x * 32;
    const int c0 = blockIdx.y * 32;
    const int tx = threadIdx.x, ty = threadIdx.y;
    const float* src = f1 + (size_t)b * CC1 * NN1;
#pragma unroll
    for (int i = 0; i < 4; i++)
        t[ty + 8 * i][tx] = src[(size_t)(c0 + ty + 8 * i) * NN1 + n0 + tx];
    __syncthreads();
    float* dst = g_f1t + (size_t)b * NN1 * CC1;
#pragma unroll
    for (int i = 0; i < 4; i++)
        dst[(size_t)(n0 + ty + 8 * i) * CC1 + c0 + tx] = t[tx][ty + 8 * i];
}

// ---------------------------------------------------------------------------
// Kernel: transpose features2 [B][C2][N2] into X[:, C1:CIN]
// grid (N2/32, C2/32, B), block (32, 8)
// ---------------------------------------------------------------------------
__global__ __launch_bounds__(256) void concat_f2_kernel(const float* __restrict__ f2) {
    __shared__ float t[32][33];
    const int b  = blockIdx.z;
    const int n0 = blockIdx.x * 32;
    const int c0 = blockIdx.y * 32;
    const int tx = threadIdx.x, ty = threadIdx.y;
    const float* src = f2 + (size_t)b * CC2 * NN2;
#pragma unroll
    for (int i = 0; i < 4; i++)
        t[ty + 8 * i][tx] = src[(size_t)(c0 + ty + 8 * i) * NN2 + n0 + tx];
    __syncthreads();
    float* dst = g_X + (size_t)b * NN2 * CIN;
#pragma unroll
    for (int i = 0; i < 4; i++)
        dst[(size_t)(n0 + ty + 8 * i) * CIN + CC1 + c0 + tx] = t[tx][ty + 8 * i];
}

// ---------------------------------------------------------------------------
// Kernel: 3-NN + inverse-distance interpolation -> X[:, 0:C1]
// grid (N2/256, B), block 256.
//
// Distance arithmetic mirrors the reference's fp32 op sequence BIT-EXACTLY:
//   s2 = fl(fl(x^2 + y^2) + z^2)          (elementwise square + 3-way reduce)
//   dot = fma(z,z', fma(y,y', fl(x*x')))  (K=3 einsum: ascending FMA chain,
//                                          how both Eigen and cuBLAS do it)
//   d = fl(fl(s2 + s1) - fl(2*dot))       (separate add / mul / sub HLO ops)
// All via __f*_rn intrinsics so nvcc cannot re-contract. This makes our
// top-3 ordering identical to the reference's top_k ordering (strict-< scan
// == lower-index-first stable ties), eliminating neighbor-set flips.
// ---------------------------------------------------------------------------
__global__ __launch_bounds__(256) void knn_interp_kernel(const float* __restrict__ p1,
                                                         const float* __restrict__ p2) {
    __shared__ float4 sp[NN1];          // (x, y, z, |p|^2) of reference points
    __shared__ int    s_idx[256 * 3];
    __shared__ float  s_w[256 * 3];

    const int b   = blockIdx.y;
    const int tid = threadIdx.x;

    const float* p1b = p1 + (size_t)b * 3 * NN1;
    for (int i = tid; i < NN1; i += 256) {
        float x = p1b[i], y = p1b[NN1 + i], z = p1b[2 * NN1 + i];
        float n = __fadd_rn(__fadd_rn(__fmul_rn(x, x), __fmul_rn(y, y)),
                            __fmul_rn(z, z));
        sp[i] = make_float4(x, y, z, n);
    }
    __syncthreads();

    const int q = blockIdx.x * 256 + tid;
    const float* p2b = p2 + (size_t)b * 3 * NN2;
    const float qx = p2b[q], qy = p2b[NN2 + q], qz = p2b[2 * NN2 + q];
    const float qn = __fadd_rn(__fadd_rn(__fmul_rn(qx, qx), __fmul_rn(qy, qy)),
                               __fmul_rn(qz, qz));

    float d0 = 1e30f, d1 = 1e30f, d2 = 1e30f;
    int   i0 = 0, i1 = 0, i2 = 0;
#pragma unroll 4
    for (int n = 0; n < NN1; n++) {
        const float4 f = sp[n];                       // uniform address -> broadcast LDS
        const float dot = __fmaf_rn(qz, f.z,
                          __fmaf_rn(qy, f.y, __fmul_rn(qx, f.x)));
        const float d = __fsub_rn(__fadd_rn(qn, f.w), __fadd_rn(dot, dot));
        if (d < d2) {                                  // strict < keeps earlier index (matches top_k ties)
            if (d < d1) {
                d2 = d1; i2 = i1;
                if (d < d0) { d1 = d0; i1 = i0; d0 = d; i0 = n; }
                else        { d1 = d;  i1 = n; }
            } else { d2 = d; i2 = n; }
        }
    }
    // weights: match reference exactly (rn divisions, ascending-slot sum)
    const float v0 = __fdiv_rn(1.f, fmaxf(d0, 1e-10f));
    const float v1 = __fdiv_rn(1.f, fmaxf(d1, 1e-10f));
    const float v2 = __fdiv_rn(1.f, fmaxf(d2, 1e-10f));
    const float s  = __fadd_rn(__fadd_rn(v0, v1), v2);
    s_idx[tid * 3 + 0] = i0; s_idx[tid * 3 + 1] = i1; s_idx[tid * 3 + 2] = i2;
    s_w[tid * 3 + 0] = __fdiv_rn(v0, s);
    s_w[tid * 3 + 1] = __fdiv_rn(v1, s);
    s_w[tid * 3 + 2] = __fdiv_rn(v2, s);
    __syncthreads();

    // Coalesced gather: thread = channel, loop over this block's 256 queries.
    // Un-contracted mul/add in reference order -> X bit-exact vs reference.
    const float* f1t = g_f1t + (size_t)b * NN1 * CC1;
    float* xout = g_X + ((size_t)b * NN2 + (size_t)blockIdx.x * 256) * CIN;
    const int c = tid;
    for (int qq = 0; qq < 256; qq++) {
        const int   a0 = s_idx[qq * 3 + 0], a1 = s_idx[qq * 3 + 1], a2 = s_idx[qq * 3 + 2];
        const float w0 = s_w[qq * 3 + 0],  w1 = s_w[qq * 3 + 1],  w2 = s_w[qq * 3 + 2];
        const float t0 = __fmul_rn(f1t[(size_t)a0 * CC1 + c], w0);
        const float t1 = __fmul_rn(f1t[(size_t)a1 * CC1 + c], w1);
        const float t2 = __fmul_rn(f1t[(size_t)a2 * CC1 + c], w2);
        xout[(size_t)qq * CIN + c] = __fadd_rn(__fadd_rn(t0, t1), t2);
    }
}

// ---------------------------------------------------------------------------
// GEMM: C[M x 256] = act(A)[M x K] @ W^T + bias, with per-channel sum/sumsq
// accumulation for BN. LAYER 0: A = g_X (identity act), K=384, out g_Y1.
// LAYER 1: A = g_Y1 with BN+ReLU (g_nrm layer 0), K=256, out g_Y2.
// 128x128 tile, 256 threads, 8x8 per thread, f32x2 FFMA2 accumulation.
// grid (2, 512)  -- n-tile fastest so A panels are L2-resident on reuse.
// ---------------------------------------------------------------------------
template <int K, int LAYER>
__global__ __launch_bounds__(256) void gemm_bn_kernel(const float* __restrict__ W,
                                                      const float* __restrict__ bias) {
    __shared__ __align__(16) float As[2][8][132];
    __shared__ __align__(16) float Bs[2][8][132];
    __shared__ float s_sum[128];
    __shared__ float s_sq[128];

    const float* __restrict__ A = (LAYER == 0) ? g_X : g_Y1;
    float* __restrict__ C       = (LAYER == 0) ? g_Y1 : g_Y2;
    float* __restrict__ osum    = g_sum + LAYER * 512;
    float* __restrict__ osq     = g_sum + LAYER * 512 + 256;
    const float* __restrict__ sc = g_nrm;        // layer-0 scale (used when LAYER==1)
    const float* __restrict__ sh = g_nrm + 256;  // layer-0 shift

    const int tid = threadIdx.x;
    const int tx = tid & 15, ty = tid >> 4;
    const int n0 = blockIdx.x * 128;
    const int m0 = blockIdx.y * 128;
    const int kk = tid & 7, rr = tid >> 3;       // global-load mapping

    const float* Ab = A + (size_t)(m0 + rr) * K + kk;
    const float* Wb = W + (size_t)(n0 + rr) * K + kk;

    unsigned long long acc[8][4];
#pragma unroll
    for (int i = 0; i < 8; i++)
#pragma unroll
        for (int j = 0; j < 4; j++) acc[i][j] = 0ull;

    // preload tile 0
    float a_reg[4], w_reg[4];
#pragma unroll
    for (int i = 0; i < 4; i++) {
        float a = Ab[(size_t)(32 * i) * K];
        if (LAYER == 1) a = fmaxf(0.f, fmaf(a, sc[kk], sh[kk]));
        a_reg[i] = a;
        w_reg[i] = Wb[(size_t)(32 * i) * K];
    }
    int buf = 0;
#pragma unroll
    for (int i = 0; i < 4; i++) {
        As[0][kk][rr + 32 * i] = a_reg[i];
        Bs[0][kk][rr + 32 * i] = w_reg[i];
    }
    __syncthreads();

    const int T = K / 8;
    for (int t = 0; t < T; t++) {
        if (t + 1 < T) {
            const int kbase = (t + 1) * 8;
#pragma unroll
            for (int i = 0; i < 4; i++) {
                float a = Ab[(size_t)(32 * i) * K + kbase];
                if (LAYER == 1) a = fmaxf(0.f, fmaf(a, sc[kbase + kk], sh[kbase + kk]));
                a_reg[i] = a;
                w_reg[i] = Wb[(size_t)(32 * i) * K + kbase];
            }
        }
#pragma unroll
        for (int k = 0; k < 8; k++) {
            const float4 aA = *(const float4*)&As[buf][k][ty * 8];
            const float4 aB = *(const float4*)&As[buf][k][ty * 8 + 4];
            const ulonglong2 b01 = *(const ulonglong2*)&Bs[buf][k][tx * 8];
            const ulonglong2 b23 = *(const ulonglong2*)&Bs[buf][k][tx * 8 + 4];
            const float av[8] = {aA.x, aA.y, aA.z, aA.w, aB.x, aB.y, aB.z, aB.w};
            const unsigned long long bp[4] = {b01.x, b01.y, b23.x, b23.y};
#pragma unroll
            for (int i = 0; i < 8; i++) {
                const unsigned long long ap = pk2(av[i]);
                ffma2(acc[i][0], ap, bp[0]);
                ffma2(acc[i][1], ap, bp[1]);
                ffma2(acc[i][2], ap, bp[2]);
                ffma2(acc[i][3], ap, bp[3]);
            }
        }
        if (t + 1 < T) {
            const int nb = buf ^ 1;
#pragma unroll
            for (int i = 0; i < 4; i++) {
                As[nb][kk][rr + 32 * i] = a_reg[i];
                Bs[nb][kk][rr + 32 * i] = w_reg[i];
            }
            __syncthreads();
            buf = nb;
        }
    }

    // Epilogue: bias add, store raw Y, accumulate per-channel sum / sumsq.
    if (tid < 128) { s_sum[tid] = 0.f; s_sq[tid] = 0.f; }
    __syncthreads();

    float bsv[8];
#pragma unroll
    for (int j = 0; j < 8; j++) bsv[j] = bias[n0 + tx * 8 + j];

    float psum[8], psq[8];
#pragma unroll
    for (int j = 0; j < 8; j++) { psum[j] = 0.f; psq[j] = 0.f; }

#pragma unroll
    for (int i = 0; i < 8; i++) {
        float v[8];
#pragma unroll
        for (int j = 0; j < 4; j++) {
            const float2 p = upk2(acc[i][j]);
            v[2 * j]     = p.x + bsv[2 * j];
            v[2 * j + 1] = p.y + bsv[2 * j + 1];
        }
        const size_t row = (size_t)(m0 + ty * 8 + i);
        float4 w0 = make_float4(v[0], v[1], v[2], v[3]);
        float4 w1 = make_float4(v[4], v[5], v[6], v[7]);
        *(float4*)&C[row * HH + n0 + tx * 8]     = w0;
        *(float4*)&C[row * HH + n0 + tx * 8 + 4] = w1;
#pragma unroll
        for (int j = 0; j < 8; j++) { psum[j] += v[j]; psq[j] += v[j] * v[j]; }
    }
#pragma unroll
    for (int j = 0; j < 8; j++) {
        atomicAdd(&s_sum[tx * 8 + j], psum[j]);
        atomicAdd(&s_sq[tx * 8 + j], psq[j]);
    }
    __syncthreads();
    if (tid < 128) {
        atomicAdd(&osum[n0 + tid], s_sum[tid]);
        atomicAdd(&osq[n0 + tid], s_sq[tid]);
    }
}

// ---------------------------------------------------------------------------
// Kernel: finalize BN stats -> per-channel (scale, shift)
// ---------------------------------------------------------------------------
__global__ void stats_final_kernel(const float* __restrict__ gamma,
                                   const float* __restrict__ beta,
                                   int layer) {
    const int c = threadIdx.x;
    if (c >= HH) return;
    const float invM = 1.f / (float)MM;
    const float s = g_sum[layer * 512 + c];
    const float q = g_sum[layer * 512 + 256 + c];
    const float mean = s * invM;
    const float var = fmaxf(q * invM - mean * mean, 0.f);
    const float rstd = __frsqrt_rn(var + 1e-3f);
    const float scale = gamma[c] * rstd;
    g_nrm[layer * 512 + c] = scale;
    g_nrm[layer * 512 + 256 + c] = beta[c] - mean * scale;
}

// ---------------------------------------------------------------------------
// Kernel: layer-2 BN + ReLU + transpose -> out[B][256][N2]
// grid (N2/32, 256/32, B), block (32, 8)
// ---------------------------------------------------------------------------
__global__ __launch_bounds__(256) void out_bn_transpose_kernel(float* __restrict__ out) {
    __shared__ float t[32][33];
    const int b  = blockIdx.z;
    const int n0 = blockIdx.x * 32;
    const int c0 = blockIdx.y * 32;
    const int tx = threadIdx.x, ty = threadIdx.y;
    const float* Y = g_Y2 + (size_t)b * NN2 * HH;
#pragma unroll
    for (int i = 0; i < 4; i++) {
        const int cc = c0 + tx;
        float v = Y[(size_t)(n0 + ty + 8 * i) * HH + cc];
        v = fmaxf(0.f, fmaf(v, g_nrm[512 + cc], g_nrm[768 + cc]));
        t[ty + 8 * i][tx] = v;
    }
    __syncthreads();
    float* dst = out + (size_t)b * HH * NN2;
#pragma unroll
    for (int i = 0; i < 4; i++)
        dst[(size_t)(c0 + ty + 8 * i) * NN2 + n0 + tx] = t[tx][ty + 8 * i];
}

// ---------------------------------------------------------------------------
// Launch
// ---------------------------------------------------------------------------
extern "C" void kernel_launch(void* const* d_in, const int* in_sizes, int n_in,
                              void* d_out, int out_size) {
    (void)in_sizes; (void)n_in; (void)out_size;
    const float* points1   = (const float*)d_in[0];
    const float* points2   = (const float*)d_in[1];
    const float* features1 = (const float*)d_in[2];
    const float* features2 = (const float*)d_in[3];
    const float* W1   = (const float*)d_in[4];
    const float* b1   = (const float*)d_in[5];
    const float* gm1  = (const float*)d_in[6];
    const float* be1  = (const float*)d_in[7];
    const float* W2   = (const float*)d_in[8];
    const float* b2   = (const float*)d_in[9];
    const float* gm2  = (const float*)d_in[10];
    const float* be2  = (const float*)d_in[11];
    float* out = (float*)d_out;

    zero_stats_kernel<<<1, 256>>>();
    transpose_f1_kernel<<<dim3(NN1 / 32, CC1 / 32, BB), dim3(32, 8)>>>(features1);
    concat_f2_kernel<<<dim3(NN2 / 32, CC2 / 32, BB), dim3(32, 8)>>>(features2);
    knn_interp_kernel<<<dim3(NN2 / 256, BB), 256>>>(points1, points2);

    gemm_bn_kernel<CIN, 0><<<dim3(HH / 128, MM / 128), 256>>>(W1, b1);
    stats_final_kernel<<<1, 256>>>(gm1, be1, 0);

    gemm_bn_kernel<HH, 1><<<dim3(HH / 128, MM / 128), 256>>>(W2, b2);
    stats_final_kernel<<<1, 256>>>(gm2, be2, 1);

    out_bn_transpose_kernel<<<dim3(NN2 / 32, HH / 32, BB), dim3(32, 8)>>>(out);
}

// round 10
// speedup vs baseline: 1.4252x; 1.4252x over previous
#include <cuda_runtime.h>
#include <cuda_bf16.h>
#include <math.h>
#include <stdint.h>

// Problem constants
#define BB   16
#define NN1  1024
#define NN2  4096
#define CC1  256
#define CC2  128
#define CIN  384           // C1 + C2
#define HH   256           // H1 == H2
#define MM   (BB * NN2)    // 65536 rows through the MLP

// ---------------------------------------------------------------------------
// Scratch (device globals; no allocations allowed)
// ---------------------------------------------------------------------------
__device__ float g_f1t[(size_t)BB * NN1 * CC1];     // f1 transposed [B][N1][C1]
__device__ float g_X  [(size_t)MM * CIN];           // concat(new_feat, f2) [M][384] row-major
__device__ float g_Y1 [(size_t)HH * MM];            // layer1 pre-BN, COLUMN-major [c][m]
__device__ float g_Y2 [(size_t)HH * MM];            // layer2 pre-BN, COLUMN-major [c][m]
__device__ float g_sum[4 * HH];                     // [sum1 | sq1 | sum2 | sq2]
__device__ float g_nrm[4 * HH];                     // [sc1 | sh1 | sc2 | sh2]
__device__ unsigned short g_W1h[HH * CIN];          // W1 bf16 hi
__device__ unsigned short g_W1l[HH * CIN];          // W1 bf16 lo (residual)
__device__ unsigned short g_W2h[HH * HH];
__device__ unsigned short g_W2l[HH * HH];

// ---------------------------------------------------------------------------
// bf16 split helpers
// ---------------------------------------------------------------------------
__device__ __forceinline__ void bsplit(float x, unsigned short& h, unsigned short& l) {
    __nv_bfloat16 hb = __float2bfloat16_rn(x);
    float r = x - __bfloat162float(hb);
    __nv_bfloat16 lb = __float2bfloat16_rn(r);
    h = __bfloat16_as_ushort(hb);
    l = __bfloat16_as_ushort(lb);
}
// pack+store 4 consecutive bf16 (k-contiguous) into u16 arrays at index idx
__device__ __forceinline__ void split_store4(unsigned short* H, unsigned short* L,
                                             int idx, float4 v) {
    unsigned short h0, l0, h1, l1, h2, l2, h3, l3;
    bsplit(v.x, h0, l0); bsplit(v.y, h1, l1);
    bsplit(v.z, h2, l2); bsplit(v.w, h3, l3);
    uint2 hp = make_uint2((uint32_t)h0 | ((uint32_t)h1 << 16),
                          (uint32_t)h2 | ((uint32_t)h3 << 16));
    uint2 lp = make_uint2((uint32_t)l0 | ((uint32_t)l1 << 16),
                          (uint32_t)l2 | ((uint32_t)l3 << 16));
    *(uint2*)&H[idx] = hp;
    *(uint2*)&L[idx] = lp;
}

// mma.sync m16n8k16 bf16 -> f32 (HMMA fallback path on sm_103; sm_80+ PTX)
__device__ __forceinline__ void mma16816(float* c, const uint32_t* a, const uint32_t* b) {
    asm volatile(
        "mma.sync.aligned.m16n8k16.row.col.f32.bf16.bf16.f32 "
        "{%0,%1,%2,%3}, {%4,%5,%6,%7}, {%8,%9}, {%0,%1,%2,%3};"
        : "+f"(c[0]), "+f"(c[1]), "+f"(c[2]), "+f"(c[3])
        : "r"(a[0]), "r"(a[1]), "r"(a[2]), "r"(a[3]), "r"(b[0]), "r"(b[1]));
}

// ---------------------------------------------------------------------------
// Kernel: zero BN stat accumulators (re-zeroed every replay)
// ---------------------------------------------------------------------------
__global__ void zero_stats_kernel() {
    for (int i = threadIdx.x; i < 4 * HH; i += blockDim.x) g_sum[i] = 0.f;
}

// ---------------------------------------------------------------------------
// Kernel: split W (fp32) -> bf16 hi/lo globals (once per launch, tiny)
// ---------------------------------------------------------------------------
__global__ void split_w_kernel(const float* __restrict__ W,
                               unsigned short* __restrict__ H,
                               unsigned short* __restrict__ L, int n) {
    const int i = blockIdx.x * 256 + threadIdx.x;
    if (i < n) {
        unsigned short h, l;
        bsplit(W[i], h, l);
        H[i] = h; L[i] = l;
    }
}

// ---------------------------------------------------------------------------
// Transpose features1 [B][C1][N1] -> g_f1t [B][N1][C1]
// ---------------------------------------------------------------------------
__global__ __launch_bounds__(256) void transpose_f1_kernel(const float* __restrict__ f1) {
    __shared__ float t[32][33];
    const int b = blockIdx.z, n0 = blockIdx.x * 32, c0 = blockIdx.y * 32;
    const int tx = threadIdx.x, ty = threadIdx.y;
    const float* src = f1 + (size_t)b * CC1 * NN1;
#pragma unroll
    for (int i = 0; i < 4; i++)
        t[ty + 8 * i][tx] = src[(size_t)(c0 + ty + 8 * i) * NN1 + n0 + tx];
    __syncthreads();
    float* dst = g_f1t + (size_t)b * NN1 * CC1;
#pragma unroll
    for (int i = 0; i < 4; i++)
        dst[(size_t)(n0 + ty + 8 * i) * CC1 + c0 + tx] = t[tx][ty + 8 * i];
}

// ---------------------------------------------------------------------------
// Transpose features2 [B][C2][N2] into X[:, C1:CIN]
// ---------------------------------------------------------------------------
__global__ __launch_bounds__(256) void concat_f2_kernel(const float* __restrict__ f2) {
    __shared__ float t[32][33];
    const int b = blockIdx.z, n0 = blockIdx.x * 32, c0 = blockIdx.y * 32;
    const int tx = threadIdx.x, ty = threadIdx.y;
    const float* src = f2 + (size_t)b * CC2 * NN2;
#pragma unroll
    for (int i = 0; i < 4; i++)
        t[ty + 8 * i][tx] = src[(size_t)(c0 + ty + 8 * i) * NN2 + n0 + tx];
    __syncthreads();
    float* dst = g_X + (size_t)b * NN2 * CIN;
#pragma unroll
    for (int i = 0; i < 4; i++)
        dst[(size_t)(n0 + ty + 8 * i) * CIN + CC1 + c0 + tx] = t[tx][ty + 8 * i];
}

// ---------------------------------------------------------------------------
// 3-NN + inverse-distance interpolation -> X[:, 0:C1]
// 512 blocks (128 queries/block), 2 threads per query each scanning 512 refs,
// then a tie-stable 3-way merge (half 0 preferred on ties = lower index,
// matching top_k's stable order). Distance arithmetic bit-exact vs reference.
// ---------------------------------------------------------------------------
__global__ __launch_bounds__(256) void knn_interp_kernel(const float* __restrict__ p1,
                                                         const float* __restrict__ p2) {
    __shared__ float4 sp[NN1];
    __shared__ float  s_bd[2 * 128 * 3];
    __shared__ int    s_bi[2 * 128 * 3];
    __shared__ float  s_w[128 * 3];
    __shared__ int    s_idx[128 * 3];

    const int b    = blockIdx.y;
    const int tid  = threadIdx.x;
    const int ql   = tid & 127;
    const int half = tid >> 7;
    const int q0   = blockIdx.x * 128;

    const float* p1b = p1 + (size_t)b * 3 * NN1;
    for (int i = tid; i < NN1; i += 256) {
        float x = p1b[i], y = p1b[NN1 + i], z = p1b[2 * NN1 + i];
        float n = __fadd_rn(__fadd_rn(__fmul_rn(x, x), __fmul_rn(y, y)), __fmul_rn(z, z));
        sp[i] = make_float4(x, y, z, n);
    }
    __syncthreads();

    const int q = q0 + ql;
    const float* p2b = p2 + (size_t)b * 3 * NN2;
    const float qx = p2b[q], qy = p2b[NN2 + q], qz = p2b[2 * NN2 + q];
    const float qn = __fadd_rn(__fadd_rn(__fmul_rn(qx, qx), __fmul_rn(qy, qy)),
                               __fmul_rn(qz, qz));

    float d0 = 1e30f, d1 = 1e30f, d2 = 1e30f;
    int   i0 = 0, i1 = 0, i2 = 0;
    const int nbeg = half * 512;
#pragma unroll 4
    for (int n = nbeg; n < nbeg + 512; n++) {
        const float4 f = sp[n];
        const float dot = __fmaf_rn(qz, f.z, __fmaf_rn(qy, f.y, __fmul_rn(qx, f.x)));
        const float d = __fsub_rn(__fadd_rn(qn, f.w), __fadd_rn(dot, dot));
        if (d < d2) {
            if (d < d1) {
                d2 = d1; i2 = i1;
                if (d < d0) { d1 = d0; i1 = i0; d0 = d; i0 = n; }
                else        { d1 = d;  i1 = n; }
            } else { d2 = d; i2 = n; }
        }
    }
    const int base = (half * 128 + ql) * 3;
    s_bd[base + 0] = d0; s_bd[base + 1] = d1; s_bd[base + 2] = d2;
    s_bi[base + 0] = i0; s_bi[base + 1] = i1; s_bi[base + 2] = i2;
    __syncthreads();

    if (tid < 128) {
        const float* da = &s_bd[tid * 3];
        const int*   ia = &s_bi[tid * 3];
        const float* db = &s_bd[(128 + tid) * 3];
        const int*   ib = &s_bi[(128 + tid) * 3];
        float dm[3]; int im[3];
        int ai = 0, bi = 0;
#pragma unroll
        for (int s = 0; s < 3; s++) {
            const float dA = da[ai], dB = db[bi];
            if (dB < dA) { dm[s] = dB; im[s] = ib[bi]; bi++; }
            else         { dm[s] = dA; im[s] = ia[ai]; ai++; }
        }
        const float v0 = __fdiv_rn(1.f, fmaxf(dm[0], 1e-10f));
        const float v1 = __fdiv_rn(1.f, fmaxf(dm[1], 1e-10f));
        const float v2 = __fdiv_rn(1.f, fmaxf(dm[2], 1e-10f));
        const float s  = __fadd_rn(__fadd_rn(v0, v1), v2);
        s_idx[tid * 3 + 0] = im[0]; s_idx[tid * 3 + 1] = im[1]; s_idx[tid * 3 + 2] = im[2];
        s_w[tid * 3 + 0] = __fdiv_rn(v0, s);
        s_w[tid * 3 + 1] = __fdiv_rn(v1, s);
        s_w[tid * 3 + 2] = __fdiv_rn(v2, s);
    }
    __syncthreads();

    const float* f1t = g_f1t + (size_t)b * NN1 * CC1;
    float* xout = g_X + ((size_t)b * NN2 + q0) * CIN;
    const int c = tid;
    for (int qq = 0; qq < 128; qq++) {
        const int   a0 = s_idx[qq * 3 + 0], a1 = s_idx[qq * 3 + 1], a2 = s_idx[qq * 3 + 2];
        const float w0 = s_w[qq * 3 + 0],  w1 = s_w[qq * 3 + 1],  w2 = s_w[qq * 3 + 2];
        const float t0 = __fmul_rn(f1t[(size_t)a0 * CC1 + c], w0);
        const float t1 = __fmul_rn(f1t[(size_t)a1 * CC1 + c], w1);
        const float t2 = __fmul_rn(f1t[(size_t)a2 * CC1 + c], w2);
        xout[(size_t)qq * CIN + c] = __fadd_rn(__fadd_rn(t0, t1), t2);
    }
}

// ---------------------------------------------------------------------------
// mma.sync bf16-split GEMM: Y[c][m] = act(A)[m,:] . W[c,:] + bias[c]
// Error-compensated: ah*bh + al*bh + ah*bl  (fp32 accumulators).
// Block = 128 rows x 128 cols, 8 warps (2M x 4N), 64x32 per warp.
// K streamed in 32-wide chunks through padded bf16 smem tiles (stride 40
// halves). W comes pre-split (bf16 hi/lo) from global. LAYER 1 fuses layer-1
// BN+ReLU into the A converter (reads Y1 col-major, coalesced).
// Grid (2, 512): n-tile fastest so A panels are L2-resident on reuse.
// ---------------------------------------------------------------------------
#define ASTRIDE 40   // u16 stride per row (32 k + 8 pad)

template <int K, int LAYER>
__global__ __launch_bounds__(256) void gemm_mma_kernel(const float* __restrict__ bias) {
    __shared__ unsigned short Ah[128 * ASTRIDE], Al[128 * ASTRIDE];
    __shared__ unsigned short Wh[128 * ASTRIDE], Wl[128 * ASTRIDE];
    __shared__ float s_bias[128], s_sum[128], s_sq[128];

    const unsigned short* __restrict__ GWh = (LAYER == 0) ? g_W1h : g_W2h;
    const unsigned short* __restrict__ GWl = (LAYER == 0) ? g_W1l : g_W2l;
    const float* __restrict__ Ain = (LAYER == 0) ? g_X : g_Y1;
    float* __restrict__ Y    = (LAYER == 0) ? g_Y1 : g_Y2;
    float* __restrict__ osum = g_sum + LAYER * 512;
    float* __restrict__ osq  = g_sum + LAYER * 512 + 256;

    const int tid  = threadIdx.x;
    const int lane = tid & 31;
    const int wid  = tid >> 5;
    const int n0   = blockIdx.x * 128;
    const int m0   = blockIdx.y * 128;
    const int m_base = (wid & 1) * 64;
    const int n_base = (wid >> 1) * 32;

    if (tid < 128) { s_bias[tid] = bias[n0 + tid]; s_sum[tid] = 0.f; s_sq[tid] = 0.f; }

    float acc[4][4][4];
#pragma unroll
    for (int a = 0; a < 4; a++)
#pragma unroll
        for (int b = 0; b < 4; b++)
#pragma unroll
            for (int c = 0; c < 4; c++) acc[a][b][c] = 0.f;

    // global-load lane mappings
    const int arow = tid >> 1, akh = (tid & 1) * 16;   // LAYER 0: A row-major
    const int akl = tid >> 3,  amq = (tid & 7) * 16;   // LAYER 1: A col-major
    const int wrow = tid >> 1, wkh = (tid & 1) * 16;   // W bf16 rows

    float  aPf[16];
    uint4  wPh[2], wPl[2];

    // ---- prefetch chunk 0 ----
    {
        if (LAYER == 0) {
            const float* ap = Ain + (size_t)(m0 + arow) * K + akh;
#pragma unroll
            for (int j = 0; j < 4; j++) *(float4*)&aPf[4 * j] = *(const float4*)(ap + 4 * j);
        } else {
            const float* cp = Ain + (size_t)akl * MM + m0 + amq;
#pragma unroll
            for (int j = 0; j < 4; j++) *(float4*)&aPf[4 * j] = *(const float4*)(cp + 4 * j);
        }
        const unsigned short* wh = GWh + (size_t)(n0 + wrow) * K + wkh;
        const unsigned short* wl = GWl + (size_t)(n0 + wrow) * K + wkh;
        wPh[0] = *(const uint4*)wh;  wPh[1] = *(const uint4*)(wh + 8);
        wPl[0] = *(const uint4*)wl;  wPl[1] = *(const uint4*)(wl + 8);
    }

    constexpr int NCH = K / 32;
    for (int ch = 0; ch < NCH; ch++) {
        // ---- store prefetched chunk into smem ----
        if (LAYER == 0) {
#pragma unroll
            for (int j = 0; j < 4; j++)
                split_store4(Ah, Al, arow * ASTRIDE + akh + 4 * j,
                             *(const float4*)&aPf[4 * j]);
        } else {
            const int c = ch * 32 + akl;
            const float sc = g_nrm[c], sh = g_nrm[256 + c];
#pragma unroll
            for (int j = 0; j < 16; j++) {
                float v = fmaxf(0.f, fmaf(aPf[j], sc, sh));
                unsigned short h, l;
                bsplit(v, h, l);
                Ah[(amq + j) * ASTRIDE + akl] = h;
                Al[(amq + j) * ASTRIDE + akl] = l;
            }
        }
        *(uint4*)&Wh[wrow * ASTRIDE + wkh]     = wPh[0];
        *(uint4*)&Wh[wrow * ASTRIDE + wkh + 8] = wPh[1];
        *(uint4*)&Wl[wrow * ASTRIDE + wkh]     = wPl[0];
        *(uint4*)&Wl[wrow * ASTRIDE + wkh + 8] = wPl[1];
        __syncthreads();

        // ---- prefetch next chunk (LDGs overlap the MMA phase) ----
        if (ch + 1 < NCH) {
            const int kbase = (ch + 1) * 32;
            if (LAYER == 0) {
                const float* ap = Ain + (size_t)(m0 + arow) * K + kbase + akh;
#pragma unroll
                for (int j = 0; j < 4; j++) *(float4*)&aPf[4 * j] = *(const float4*)(ap + 4 * j);
            } else {
                const float* cp = Ain + (size_t)(kbase + akl) * MM + m0 + amq;
#pragma unroll
                for (int j = 0; j < 4; j++) *(float4*)&aPf[4 * j] = *(const float4*)(cp + 4 * j);
            }
            const unsigned short* wh = GWh + (size_t)(n0 + wrow) * K + kbase + wkh;
            const unsigned short* wl = GWl + (size_t)(n0 + wrow) * K + kbase + wkh;
            wPh[0] = *(const uint4*)wh;  wPh[1] = *(const uint4*)(wh + 8);
            wPl[0] = *(const uint4*)wl;  wPl[1] = *(const uint4*)(wl + 8);
        }

        // ---- MMA phase: 2 k16 steps, 3 split terms ----
#pragma unroll
        for (int kk = 0; kk < 32; kk += 16) {
            uint32_t afh[4][4], afl[4][4];
#pragma unroll
            for (int mt = 0; mt < 4; mt++) {
                const int r = m_base + mt * 16 + (lane >> 2);
                const int o = r * ASTRIDE + kk + (lane & 3) * 2;
                afh[mt][0] = *(const uint32_t*)&Ah[o];
                afh[mt][1] = *(const uint32_t*)&Ah[o + 8 * ASTRIDE];
                afh[mt][2] = *(const uint32_t*)&Ah[o + 8];
                afh[mt][3] = *(const uint32_t*)&Ah[o + 8 * ASTRIDE + 8];
                afl[mt][0] = *(const uint32_t*)&Al[o];
                afl[mt][1] = *(const uint32_t*)&Al[o + 8 * ASTRIDE];
                afl[mt][2] = *(const uint32_t*)&Al[o + 8];
                afl[mt][3] = *(const uint32_t*)&Al[o + 8 * ASTRIDE + 8];
            }
            uint32_t bfh[4][2], bfl[4][2];
#pragma unroll
            for (int nt = 0; nt < 4; nt++) {
                const int n = n_base + nt * 8 + (lane >> 2);
                const int o = n * ASTRIDE + kk + (lane & 3) * 2;
                bfh[nt][0] = *(const uint32_t*)&Wh[o];
                bfh[nt][1] = *(const uint32_t*)&Wh[o + 8];
                bfl[nt][0] = *(const uint32_t*)&Wl[o];
                bfl[nt][1] = *(const uint32_t*)&Wl[o + 8];
            }
#pragma unroll
            for (int mt = 0; mt < 4; mt++)
#pragma unroll
                for (int nt = 0; nt < 4; nt++) {
                    mma16816(acc[mt][nt], afh[mt], bfh[nt]);
                    mma16816(acc[mt][nt], afl[mt], bfh[nt]);
                    mma16816(acc[mt][nt], afh[mt], bfl[nt]);
                }
        }
        __syncthreads();
    }

    // ---- Epilogue: +bias, store Y col-major, BN partial stats ----
#pragma unroll
    for (int nt = 0; nt < 4; nt++) {
        const int n = n_base + nt * 8 + 2 * (lane & 3);
        const float b0 = s_bias[n], b1 = s_bias[n + 1];
        float cs0 = 0.f, cq0 = 0.f, cs1 = 0.f, cq1 = 0.f;
#pragma unroll
        for (int mt = 0; mt < 4; mt++) {
            const int r = m_base + mt * 16 + (lane >> 2);
            const float v0 = acc[mt][nt][0] + b0;
            const float v1 = acc[mt][nt][1] + b1;
            const float v2 = acc[mt][nt][2] + b0;
            const float v3 = acc[mt][nt][3] + b1;
            Y[(size_t)(n0 + n)     * MM + m0 + r]     = v0;
            Y[(size_t)(n0 + n + 1) * MM + m0 + r]     = v1;
            Y[(size_t)(n0 + n)     * MM + m0 + r + 8] = v2;
            Y[(size_t)(n0 + n + 1) * MM + m0 + r + 8] = v3;
            cs0 += v0 + v2; cq0 += v0 * v0 + v2 * v2;
            cs1 += v1 + v3; cq1 += v1 * v1 + v3 * v3;
        }
#pragma unroll
        for (int off = 16; off >= 4; off >>= 1) {
            cs0 += __shfl_xor_sync(0xFFFFFFFFu, cs0, off);
            cq0 += __shfl_xor_sync(0xFFFFFFFFu, cq0, off);
            cs1 += __shfl_xor_sync(0xFFFFFFFFu, cs1, off);
            cq1 += __shfl_xor_sync(0xFFFFFFFFu, cq1, off);
        }
        if (lane < 4) {
            atomicAdd(&s_sum[n], cs0); atomicAdd(&s_sq[n], cq0);
            atomicAdd(&s_sum[n + 1], cs1); atomicAdd(&s_sq[n + 1], cq1);
        }
    }
    __syncthreads();
    if (tid < 128) {
        atomicAdd(&osum[n0 + tid], s_sum[tid]);
        atomicAdd(&osq[n0 + tid], s_sq[tid]);
    }
}

// ---------------------------------------------------------------------------
// Finalize BN stats -> per-channel (scale, shift)
// ---------------------------------------------------------------------------
__global__ void stats_final_kernel(const float* __restrict__ gamma,
                                   const float* __restrict__ beta,
                                   int layer) {
    const int c = threadIdx.x;
    if (c >= HH) return;
    const float invM = 1.f / (float)MM;
    const float s = g_sum[layer * 512 + c];
    const float q = g_sum[layer * 512 + 256 + c];
    const float mean = s * invM;
    const float var = fmaxf(q * invM - mean * mean, 0.f);
    const float rstd = rsqrtf(var + 1e-3f);
    const float scale = gamma[c] * rstd;
    g_nrm[layer * 512 + c] = scale;
    g_nrm[layer * 512 + 256 + c] = beta[c] - mean * scale;
}

// ---------------------------------------------------------------------------
// Final: layer-2 BN + ReLU, Y2 col-major [c][b*4096+n] -> out[b][c][n]
// ---------------------------------------------------------------------------
__global__ __launch_bounds__(256) void out_bn_kernel(float* __restrict__ out) {
    const int m = blockIdx.x * 256 + threadIdx.x;
    const int c = blockIdx.y;
    float v = g_Y2[(size_t)c * MM + m];
    v = fmaxf(0.f, fmaf(v, g_nrm[512 + c], g_nrm[768 + c]));
    const int b = m >> 12;
    const int n = m & 4095;
    out[(size_t)b * HH * NN2 + (size_t)c * NN2 + n] = v;
}

// ---------------------------------------------------------------------------
// Launch
// ---------------------------------------------------------------------------
extern "C" void kernel_launch(void* const* d_in, const int* in_sizes, int n_in,
                              void* d_out, int out_size) {
    (void)in_sizes; (void)n_in; (void)out_size;
    const float* points1   = (const float*)d_in[0];
    const float* points2   = (const float*)d_in[1];
    const float* features1 = (const float*)d_in[2];
    const float* features2 = (const float*)d_in[3];
    const float* W1  = (const float*)d_in[4];
    const float* b1  = (const float*)d_in[5];
    const float* gm1 = (const float*)d_in[6];
    const float* be1 = (const float*)d_in[7];
    const float* W2  = (const float*)d_in[8];
    const float* b2  = (const float*)d_in[9];
    const float* gm2 = (const float*)d_in[10];
    const float* be2 = (const float*)d_in[11];
    float* out = (float*)d_out;

    unsigned short *w1h, *w1l, *w2h, *w2l;
    cudaGetSymbolAddress((void**)&w1h, g_W1h);
    cudaGetSymbolAddress((void**)&w1l, g_W1l);
    cudaGetSymbolAddress((void**)&w2h, g_W2h);
    cudaGetSymbolAddress((void**)&w2l, g_W2l);

    zero_stats_kernel<<<1, 256>>>();
    split_w_kernel<<<(HH * CIN + 255) / 256, 256>>>(W1, w1h, w1l, HH * CIN);
    split_w_kernel<<<(HH * HH + 255) / 256, 256>>>(W2, w2h, w2l, HH * HH);
    transpose_f1_kernel<<<dim3(NN1 / 32, CC1 / 32, BB), dim3(32, 8)>>>(features1);
    concat_f2_kernel<<<dim3(NN2 / 32, CC2 / 32, BB), dim3(32, 8)>>>(features2);
    knn_interp_kernel<<<dim3(NN2 / 128, BB), 256>>>(points1, points2);

    gemm_mma_kernel<CIN, 0><<<dim3(2, MM / 128), 256>>>(b1);
    stats_final_kernel<<<1, 256>>>(gm1, be1, 0);

    gemm_mma_kernel<HH, 1><<<dim3(2, MM / 128), 256>>>(b2);
    stats_final_kernel<<<1, 256>>>(gm2, be2, 1);

    out_bn_kernel<<<dim3(MM / 256, HH), 256>>>(out);
}

// round 11
// speedup vs baseline: 1.6952x; 1.1894x over previous
#include <cuda_runtime.h>
#include <cuda_bf16.h>
#include <math.h>
#include <stdint.h>

// Problem constants
#define BB   16
#define NN1  1024
#define NN2  4096
#define CC1  256
#define CC2  128
#define CIN  384           // C1 + C2
#define HH   256           // H1 == H2
#define MM   (BB * NN2)    // 65536 rows through the MLP

// ---------------------------------------------------------------------------
// Scratch (device globals; no allocations allowed)
// ---------------------------------------------------------------------------
__device__ float g_f1t[(size_t)BB * NN1 * CC1];     // f1 transposed [B][N1][C1]
__device__ __align__(256) unsigned short g_Xh[(size_t)MM * CIN];  // X bf16 hi, row-major
__device__ __align__(256) unsigned short g_Xl[(size_t)MM * CIN];  // X bf16 lo
__device__ float g_Y1 [(size_t)HH * MM];            // layer1 pre-BN, COLUMN-major [c][m]
__device__ __align__(256) unsigned short g_Y1h[(size_t)MM * HH];  // act(Y1) bf16 hi, row-major
__device__ __align__(256) unsigned short g_Y1l[(size_t)MM * HH];  // act(Y1) bf16 lo
__device__ float g_Y2 [(size_t)HH * MM];            // layer2 pre-BN, COLUMN-major [c][m]
__device__ float g_sum[4 * HH];                     // [sum1 | sq1 | sum2 | sq2]
__device__ float g_nrm[4 * HH];                     // [sc1 | sh1 | sc2 | sh2]
__device__ __align__(256) unsigned short g_W1h[HH * CIN];
__device__ __align__(256) unsigned short g_W1l[HH * CIN];
__device__ __align__(256) unsigned short g_W2h[HH * HH];
__device__ __align__(256) unsigned short g_W2l[HH * HH];

// ---------------------------------------------------------------------------
// Helpers
// ---------------------------------------------------------------------------
__device__ __forceinline__ uint32_t smem_to_u32(const void* p) {
    uint32_t a;
    asm("{ .reg .u64 t; cvta.to.shared.u64 t, %1; cvt.u32.u64 %0, t; }" : "=r"(a) : "l"(p));
    return a;
}
__device__ __forceinline__ void bsplit(float x, unsigned short& h, unsigned short& l) {
    __nv_bfloat16 hb = __float2bfloat16_rn(x);
    float r = x - __bfloat162float(hb);
    __nv_bfloat16 lb = __float2bfloat16_rn(r);
    h = __bfloat16_as_ushort(hb);
    l = __bfloat16_as_ushort(lb);
}
__device__ __forceinline__ void cpa16(uint32_t d, const void* s) {
    asm volatile("cp.async.cg.shared.global [%0], [%1], 16;" :: "r"(d), "l"(s));
}
__device__ __forceinline__ void cp_commit() {
    asm volatile("cp.async.commit_group;");
}
template <int N>
__device__ __forceinline__ void cp_wait() {
    asm volatile("cp.async.wait_group %0;" :: "n"(N));
}
// mma.sync m16n8k16 bf16 -> f32 (HMMA path on sm_103; sm_80+ PTX)
__device__ __forceinline__ void mma16816(float* c, const uint32_t* a, const uint32_t* b) {
    asm volatile(
        "mma.sync.aligned.m16n8k16.row.col.f32.bf16.bf16.f32 "
        "{%0,%1,%2,%3}, {%4,%5,%6,%7}, {%8,%9}, {%0,%1,%2,%3};"
        : "+f"(c[0]), "+f"(c[1]), "+f"(c[2]), "+f"(c[3])
        : "r"(a[0]), "r"(a[1]), "r"(a[2]), "r"(a[3]), "r"(b[0]), "r"(b[1]));
}

// ---------------------------------------------------------------------------
// Zero BN stat accumulators (re-zeroed every replay)
// ---------------------------------------------------------------------------
__global__ void zero_stats_kernel() {
    for (int i = threadIdx.x; i < 4 * HH; i += blockDim.x) g_sum[i] = 0.f;
}

// ---------------------------------------------------------------------------
// Split W (fp32) -> bf16 hi/lo globals (tiny, once per launch)
// ---------------------------------------------------------------------------
__global__ void split_w_kernel(const float* __restrict__ W,
                               unsigned short* __restrict__ H,
                               unsigned short* __restrict__ L, int n) {
    const int i = blockIdx.x * 256 + threadIdx.x;
    if (i < n) {
        unsigned short h, l;
        bsplit(W[i], h, l);
        H[i] = h; L[i] = l;
    }
}

// ---------------------------------------------------------------------------
// Transpose features1 [B][C1][N1] -> g_f1t [B][N1][C1]  (fp32, for gather)
// ---------------------------------------------------------------------------
__global__ __launch_bounds__(256) void transpose_f1_kernel(const float* __restrict__ f1) {
    __shared__ float t[32][33];
    const int b = blockIdx.z, n0 = blockIdx.x * 32, c0 = blockIdx.y * 32;
    const int tx = threadIdx.x, ty = threadIdx.y;
    const float* src = f1 + (size_t)b * CC1 * NN1;
#pragma unroll
    for (int i = 0; i < 4; i++)
        t[ty + 8 * i][tx] = src[(size_t)(c0 + ty + 8 * i) * NN1 + n0 + tx];
    __syncthreads();
    float* dst = g_f1t + (size_t)b * NN1 * CC1;
#pragma unroll
    for (int i = 0; i < 4; i++)
        dst[(size_t)(n0 + ty + 8 * i) * CC1 + c0 + tx] = t[tx][ty + 8 * i];
}

// ---------------------------------------------------------------------------
// Transpose features2 [B][C2][N2] into X[:, C1:CIN], written bf16-split
// ---------------------------------------------------------------------------
__global__ __launch_bounds__(256) void concat_f2_kernel(const float* __restrict__ f2) {
    __shared__ float t[32][33];
    const int b = blockIdx.z, n0 = blockIdx.x * 32, c0 = blockIdx.y * 32;
    const int tx = threadIdx.x, ty = threadIdx.y;
    const float* src = f2 + (size_t)b * CC2 * NN2;
#pragma unroll
    for (int i = 0; i < 4; i++)
        t[ty + 8 * i][tx] = src[(size_t)(c0 + ty + 8 * i) * NN2 + n0 + tx];
    __syncthreads();
#pragma unroll
    for (int i = 0; i < 4; i++) {
        const size_t m = (size_t)b * NN2 + n0 + ty + 8 * i;
        unsigned short h, l;
        bsplit(t[tx][ty + 8 * i], h, l);
        g_Xh[m * CIN + CC1 + c0 + tx] = h;
        g_Xl[m * CIN + CC1 + c0 + tx] = l;
    }
}

// ---------------------------------------------------------------------------
// 3-NN + inverse-distance interpolation -> X[:, 0:C1] (bf16-split)
// 512 blocks (128 queries/block), 2 threads per query each scanning 512 refs,
// then a tie-stable 3-way merge (half 0 preferred on ties = lower index,
// matching top_k's stable order). Distance arithmetic bit-exact vs reference.
// ---------------------------------------------------------------------------
__global__ __launch_bounds__(256) void knn_interp_kernel(const float* __restrict__ p1,
                                                         const float* __restrict__ p2) {
    __shared__ float4 sp[NN1];
    __shared__ float  s_bd[2 * 128 * 3];
    __shared__ int    s_bi[2 * 128 * 3];
    __shared__ float  s_w[128 * 3];
    __shared__ int    s_idx[128 * 3];

    const int b    = blockIdx.y;
    const int tid  = threadIdx.x;
    const int ql   = tid & 127;
    const int half = tid >> 7;
    const int q0   = blockIdx.x * 128;

    const float* p1b = p1 + (size_t)b * 3 * NN1;
    for (int i = tid; i < NN1; i += 256) {
        float x = p1b[i], y = p1b[NN1 + i], z = p1b[2 * NN1 + i];
        float n = __fadd_rn(__fadd_rn(__fmul_rn(x, x), __fmul_rn(y, y)), __fmul_rn(z, z));
        sp[i] = make_float4(x, y, z, n);
    }
    __syncthreads();

    const int q = q0 + ql;
    const float* p2b = p2 + (size_t)b * 3 * NN2;
    const float qx = p2b[q], qy = p2b[NN2 + q], qz = p2b[2 * NN2 + q];
    const float qn = __fadd_rn(__fadd_rn(__fmul_rn(qx, qx), __fmul_rn(qy, qy)),
                               __fmul_rn(qz, qz));

    float d0 = 1e30f, d1 = 1e30f, d2 = 1e30f;
    int   i0 = 0, i1 = 0, i2 = 0;
    const int nbeg = half * 512;
#pragma unroll 4
    for (int n = nbeg; n < nbeg + 512; n++) {
        const float4 f = sp[n];
        const float dot = __fmaf_rn(qz, f.z, __fmaf_rn(qy, f.y, __fmul_rn(qx, f.x)));
        const float d = __fsub_rn(__fadd_rn(qn, f.w), __fadd_rn(dot, dot));
        if (d < d2) {
            if (d < d1) {
                d2 = d1; i2 = i1;
                if (d < d0) { d1 = d0; i1 = i0; d0 = d; i0 = n; }
                else        { d1 = d;  i1 = n; }
            } else { d2 = d; i2 = n; }
        }
    }
    const int base = (half * 128 + ql) * 3;
    s_bd[base + 0] = d0; s_bd[base + 1] = d1; s_bd[base + 2] = d2;
    s_bi[base + 0] = i0; s_bi[base + 1] = i1; s_bi[base + 2] = i2;
    __syncthreads();

    if (tid < 128) {
        const float* da = &s_bd[tid * 3];
        const int*   ia = &s_bi[tid * 3];
        const float* db = &s_bd[(128 + tid) * 3];
        const int*   ib = &s_bi[(128 + tid) * 3];
        float dm[3]; int im[3];
        int ai = 0, bi = 0;
#pragma unroll
        for (int s = 0; s < 3; s++) {
            const float dA = da[ai], dB = db[bi];
            if (dB < dA) { dm[s] = dB; im[s] = ib[bi]; bi++; }
            else         { dm[s] = dA; im[s] = ia[ai]; ai++; }
        }
        const float v0 = __fdiv_rn(1.f, fmaxf(dm[0], 1e-10f));
        const float v1 = __fdiv_rn(1.f, fmaxf(dm[1], 1e-10f));
        const float v2 = __fdiv_rn(1.f, fmaxf(dm[2], 1e-10f));
        const float s  = __fadd_rn(__fadd_rn(v0, v1), v2);
        s_idx[tid * 3 + 0] = im[0]; s_idx[tid * 3 + 1] = im[1]; s_idx[tid * 3 + 2] = im[2];
        s_w[tid * 3 + 0] = __fdiv_rn(v0, s);
        s_w[tid * 3 + 1] = __fdiv_rn(v1, s);
        s_w[tid * 3 + 2] = __fdiv_rn(v2, s);
    }
    __syncthreads();

    const float* f1t = g_f1t + (size_t)b * NN1 * CC1;
    const size_t mrow0 = (size_t)b * NN2 + q0;
    const int c = tid;
    for (int qq = 0; qq < 128; qq++) {
        const int   a0 = s_idx[qq * 3 + 0], a1 = s_idx[qq * 3 + 1], a2 = s_idx[qq * 3 + 2];
        const float w0 = s_w[qq * 3 + 0],  w1 = s_w[qq * 3 + 1],  w2 = s_w[qq * 3 + 2];
        const float t0 = __fmul_rn(f1t[(size_t)a0 * CC1 + c], w0);
        const float t1 = __fmul_rn(f1t[(size_t)a1 * CC1 + c], w1);
        const float t2 = __fmul_rn(f1t[(size_t)a2 * CC1 + c], w2);
        const float v  = __fadd_rn(__fadd_rn(t0, t1), t2);
        unsigned short h, l;
        bsplit(v, h, l);
        g_Xh[(mrow0 + qq) * CIN + c] = h;
        g_Xl[(mrow0 + qq) * CIN + c] = l;
    }
}

// ---------------------------------------------------------------------------
// mma.sync bf16-split GEMM: Y[c][m] = A[m,:] . W[c,:] + bias[c]
// A and W arrive pre-split (bf16 hi/lo) row-major; zero arithmetic in the
// load path. cp.async double-buffered (2 stages x 4 tiles, 82 KB smem).
// 3-term compensation: ah*bh + al*bh + ah*bl into fp32 accumulators.
// Block = 128 rows x 128 cols, 8 warps (2M x 4N), 64x32 per warp.
// Grid (2, 512): n-tile fastest so A panels are L2-resident on reuse.
// Epilogue: +bias, store Y col-major (coalesced), BN stats via shfl + atomics.
// ---------------------------------------------------------------------------
#define ASTRIDE 40                    // u16 stride per row (32 k + 8 pad)
#define TILE_U16 (128 * ASTRIDE)      // 5120 u16 = 10240 B
#define STAGE_U16 (4 * TILE_U16)      // 20480 u16 = 40960 B
#define GEMM_SMEM (2 * STAGE_U16 * 2 + 3 * 128 * 4)   // 83456 B

template <int K>
__global__ __launch_bounds__(256)
void gemm_mma_kernel(const unsigned short* __restrict__ GAh,
                     const unsigned short* __restrict__ GAl,
                     const unsigned short* __restrict__ GWh,
                     const unsigned short* __restrict__ GWl,
                     const float* __restrict__ bias,
                     float* __restrict__ Y,
                     float* __restrict__ osum,
                     float* __restrict__ osq) {
    extern __shared__ char smem[];
    const uint32_t sb = smem_to_u32(smem);
    unsigned short* su16 = (unsigned short*)smem;
    float* s_bias = (float*)(smem + 2 * STAGE_U16 * 2);
    float* s_sum  = s_bias + 128;
    float* s_sq   = s_sum + 128;

    const int tid  = threadIdx.x;
    const int lane = tid & 31;
    const int wid  = tid >> 5;
    const int n0   = blockIdx.x * 128;
    const int m0   = blockIdx.y * 128;
    const int m_base = (wid & 1) * 64;
    const int n_base = (wid >> 1) * 32;

    if (tid < 128) { s_bias[tid] = bias[n0 + tid]; s_sum[tid] = 0.f; s_sq[tid] = 0.f; }

    float acc[4][4][4];
#pragma unroll
    for (int a = 0; a < 4; a++)
#pragma unroll
        for (int b = 0; b < 4; b++)
#pragma unroll
            for (int c = 0; c < 4; c++) acc[a][b][c] = 0.f;

    // cp.async mapping: each thread copies 2x16B per tile (rows tid>>1)
    const int crow = tid >> 1;
    const int ckoff = (tid & 1) * 16;                    // u16 offset within 32-k chunk

    auto issue = [&](int ch, int st) {
        const int kb = ch * 32 + ckoff;
        const unsigned short* a_h = GAh + (size_t)(m0 + crow) * K + kb;
        const unsigned short* a_l = GAl + (size_t)(m0 + crow) * K + kb;
        const unsigned short* w_h = GWh + (size_t)(n0 + crow) * K + kb;
        const unsigned short* w_l = GWl + (size_t)(n0 + crow) * K + kb;
        const uint32_t so = sb + (uint32_t)(st * STAGE_U16 + crow * ASTRIDE + ckoff) * 2u;
        cpa16(so, a_h);                          cpa16(so + 16, a_h + 8);
        cpa16(so + TILE_U16 * 2, a_l);           cpa16(so + TILE_U16 * 2 + 16, a_l + 8);
        cpa16(so + TILE_U16 * 4, w_h);           cpa16(so + TILE_U16 * 4 + 16, w_h + 8);
        cpa16(so + TILE_U16 * 6, w_l);           cpa16(so + TILE_U16 * 6 + 16, w_l + 8);
        cp_commit();
    };

    constexpr int NCH = K / 32;
    issue(0, 0);
    int buf = 0;
    for (int ch = 0; ch < NCH; ch++) {
        if (ch + 1 < NCH) { issue(ch + 1, buf ^ 1); cp_wait<1>(); }
        else              { cp_wait<0>(); }
        __syncthreads();

        const unsigned short* Ah = su16 + buf * STAGE_U16;
        const unsigned short* Al = Ah + TILE_U16;
        const unsigned short* Wh = Al + TILE_U16;
        const unsigned short* Wl = Wh + TILE_U16;

#pragma unroll
        for (int kk = 0; kk < 32; kk += 16) {
            uint32_t afh[4][4], afl[4][4];
#pragma unroll
            for (int mt = 0; mt < 4; mt++) {
                const int r = m_base + mt * 16 + (lane >> 2);
                const int o = r * ASTRIDE + kk + (lane & 3) * 2;
                afh[mt][0] = *(const uint32_t*)&Ah[o];
                afh[mt][1] = *(const uint32_t*)&Ah[o + 8 * ASTRIDE];
                afh[mt][2] = *(const uint32_t*)&Ah[o + 8];
                afh[mt][3] = *(const uint32_t*)&Ah[o + 8 * ASTRIDE + 8];
                afl[mt][0] = *(const uint32_t*)&Al[o];
                afl[mt][1] = *(const uint32_t*)&Al[o + 8 * ASTRIDE];
                afl[mt][2] = *(const uint32_t*)&Al[o + 8];
                afl[mt][3] = *(const uint32_t*)&Al[o + 8 * ASTRIDE + 8];
            }
            uint32_t bfh[4][2], bfl[4][2];
#pragma unroll
            for (int nt = 0; nt < 4; nt++) {
                const int n = n_base + nt * 8 + (lane >> 2);
                const int o = n * ASTRIDE + kk + (lane & 3) * 2;
                bfh[nt][0] = *(const uint32_t*)&Wh[o];
                bfh[nt][1] = *(const uint32_t*)&Wh[o + 8];
                bfl[nt][0] = *(const uint32_t*)&Wl[o];
                bfl[nt][1] = *(const uint32_t*)&Wl[o + 8];
            }
#pragma unroll
            for (int mt = 0; mt < 4; mt++)
#pragma unroll
                for (int nt = 0; nt < 4; nt++) {
                    mma16816(acc[mt][nt], afh[mt], bfh[nt]);
                    mma16816(acc[mt][nt], afl[mt], bfh[nt]);
                    mma16816(acc[mt][nt], afh[mt], bfl[nt]);
                }
        }
        __syncthreads();
        buf ^= 1;
    }

    // ---- Epilogue: +bias, store Y col-major, BN partial stats ----
#pragma unroll
    for (int nt = 0; nt < 4; nt++) {
        const int n = n_base + nt * 8 + 2 * (lane & 3);
        const float b0 = s_bias[n], b1 = s_bias[n + 1];
        float cs0 = 0.f, cq0 = 0.f, cs1 = 0.f, cq1 = 0.f;
#pragma unroll
        for (int mt = 0; mt < 4; mt++) {
            const int r = m_base + mt * 16 + (lane >> 2);
            const float v0 = acc[mt][nt][0] + b0;
            const float v1 = acc[mt][nt][1] + b1;
            const float v2 = acc[mt][nt][2] + b0;
            const float v3 = acc[mt][nt][3] + b1;
            Y[(size_t)(n0 + n)     * MM + m0 + r]     = v0;
            Y[(size_t)(n0 + n + 1) * MM + m0 + r]     = v1;
            Y[(size_t)(n0 + n)     * MM + m0 + r + 8] = v2;
            Y[(size_t)(n0 + n + 1) * MM + m0 + r + 8] = v3;
            cs0 += v0 + v2; cq0 += v0 * v0 + v2 * v2;
            cs1 += v1 + v3; cq1 += v1 * v1 + v3 * v3;
        }
#pragma unroll
        for (int off = 16; off >= 4; off >>= 1) {
            cs0 += __shfl_xor_sync(0xFFFFFFFFu, cs0, off);
            cq0 += __shfl_xor_sync(0xFFFFFFFFu, cq0, off);
            cs1 += __shfl_xor_sync(0xFFFFFFFFu, cs1, off);
            cq1 += __shfl_xor_sync(0xFFFFFFFFu, cq1, off);
        }
        if (lane < 4) {
            atomicAdd(&s_sum[n], cs0); atomicAdd(&s_sq[n], cq0);
            atomicAdd(&s_sum[n + 1], cs1); atomicAdd(&s_sq[n + 1], cq1);
        }
    }
    __syncthreads();
    if (tid < 128) {
        atomicAdd(&osum[n0 + tid], s_sum[tid]);
        atomicAdd(&osq[n0 + tid], s_sq[tid]);
    }
}

// ---------------------------------------------------------------------------
// Finalize BN stats -> per-channel (scale, shift)
// ---------------------------------------------------------------------------
__global__ void stats_final_kernel(const float* __restrict__ gamma,
                                   const float* __restrict__ beta,
                                   int layer) {
    const int c = threadIdx.x;
    if (c >= HH) return;
    const float invM = 1.f / (float)MM;
    const float s = g_sum[layer * 512 + c];
    const float q = g_sum[layer * 512 + 256 + c];
    const float mean = s * invM;
    const float var = fmaxf(q * invM - mean * mean, 0.f);
    const float rstd = rsqrtf(var + 1e-3f);
    const float scale = gamma[c] * rstd;
    g_nrm[layer * 512 + c] = scale;
    g_nrm[layer * 512 + 256 + c] = beta[c] - mean * scale;
}

// ---------------------------------------------------------------------------
// prep2: Y1 col-major fp32 -> BN+ReLU -> bf16 split, transposed to
// row-major [m][HH]. grid (MM/32, HH/32), block (32, 8); both sides coalesced.
// ---------------------------------------------------------------------------
__global__ __launch_bounds__(256) void prep2_kernel() {
    __shared__ float t[32][33];
    const int m0 = blockIdx.x * 32, c0 = blockIdx.y * 32;
    const int tx = threadIdx.x, ty = threadIdx.y;
#pragma unroll
    for (int i = 0; i < 4; i++) {
        const int cc = c0 + ty + 8 * i;
        float v = g_Y1[(size_t)cc * MM + m0 + tx];
        t[ty + 8 * i][tx] = fmaxf(0.f, fmaf(v, g_nrm[cc], g_nrm[256 + cc]));
    }
    __syncthreads();
#pragma unroll
    for (int i = 0; i < 4; i++) {
        const size_t m = (size_t)(m0 + ty + 8 * i);
        unsigned short h, l;
        bsplit(t[tx][ty + 8 * i], h, l);
        g_Y1h[m * HH + c0 + tx] = h;
        g_Y1l[m * HH + c0 + tx] = l;
    }
}

// ---------------------------------------------------------------------------
// Final: layer-2 BN + ReLU, Y2 col-major [c][b*4096+n] -> out[b][c][n]
// ---------------------------------------------------------------------------
__global__ __launch_bounds__(256) void out_bn_kernel(float* __restrict__ out) {
    const int m = blockIdx.x * 256 + threadIdx.x;
    const int c = blockIdx.y;
    float v = g_Y2[(size_t)c * MM + m];
    v = fmaxf(0.f, fmaf(v, g_nrm[512 + c], g_nrm[768 + c]));
    const int b = m >> 12;
    const int n = m & 4095;
    out[(size_t)b * HH * NN2 + (size_t)c * NN2 + n] = v;
}

// ---------------------------------------------------------------------------
// Launch
// ---------------------------------------------------------------------------
extern "C" void kernel_launch(void* const* d_in, const int* in_sizes, int n_in,
                              void* d_out, int out_size) {
    (void)in_sizes; (void)n_in; (void)out_size;
    const float* points1   = (const float*)d_in[0];
    const float* points2   = (const float*)d_in[1];
    const float* features1 = (const float*)d_in[2];
    const float* features2 = (const float*)d_in[3];
    const float* W1  = (const float*)d_in[4];
    const float* b1  = (const float*)d_in[5];
    const float* gm1 = (const float*)d_in[6];
    const float* be1 = (const float*)d_in[7];
    const float* W2  = (const float*)d_in[8];
    const float* b2  = (const float*)d_in[9];
    const float* gm2 = (const float*)d_in[10];
    const float* be2 = (const float*)d_in[11];
    float* out = (float*)d_out;

    unsigned short *w1h, *w1l, *w2h, *w2l, *xh, *xl, *y1h, *y1l;
    float *y1, *y2, *gsum;
    cudaGetSymbolAddress((void**)&w1h, g_W1h);
    cudaGetSymbolAddress((void**)&w1l, g_W1l);
    cudaGetSymbolAddress((void**)&w2h, g_W2h);
    cudaGetSymbolAddress((void**)&w2l, g_W2l);
    cudaGetSymbolAddress((void**)&xh,  g_Xh);
    cudaGetSymbolAddress((void**)&xl,  g_Xl);
    cudaGetSymbolAddress((void**)&y1h, g_Y1h);
    cudaGetSymbolAddress((void**)&y1l, g_Y1l);
    cudaGetSymbolAddress((void**)&y1,  g_Y1);
    cudaGetSymbolAddress((void**)&y2,  g_Y2);
    cudaGetSymbolAddress((void**)&gsum, g_sum);

    cudaFuncSetAttribute(gemm_mma_kernel<CIN>,
                         cudaFuncAttributeMaxDynamicSharedMemorySize, GEMM_SMEM);
    cudaFuncSetAttribute(gemm_mma_kernel<HH>,
                         cudaFuncAttributeMaxDynamicSharedMemorySize, GEMM_SMEM);

    zero_stats_kernel<<<1, 256>>>();
    split_w_kernel<<<(HH * CIN + 255) / 256, 256>>>(W1, w1h, w1l, HH * CIN);
    split_w_kernel<<<(HH * HH + 255) / 256, 256>>>(W2, w2h, w2l, HH * HH);
    transpose_f1_kernel<<<dim3(NN1 / 32, CC1 / 32, BB), dim3(32, 8)>>>(features1);
    concat_f2_kernel<<<dim3(NN2 / 32, CC2 / 32, BB), dim3(32, 8)>>>(features2);
    knn_interp_kernel<<<dim3(NN2 / 128, BB), 256>>>(points1, points2);

    gemm_mma_kernel<CIN><<<dim3(2, MM / 128), 256, GEMM_SMEM>>>(
        xh, xl, w1h, w1l, b1, y1, gsum, gsum + 256);
    stats_final_kernel<<<1, 256>>>(gm1, be1, 0);
    prep2_kernel<<<dim3(MM / 32, HH / 32), dim3(32, 8)>>>();

    gemm_mma_kernel<HH><<<dim3(2, MM / 128), 256, GEMM_SMEM>>>(
        y1h, y1l, w2h, w2l, b2, y2, gsum + 512, gsum + 768);
    stats_final_kernel<<<1, 256>>>(gm2, be2, 1);

    out_bn_kernel<<<dim3(MM / 256, HH), 256>>>(out);
}

// round 12
// speedup vs baseline: 1.8406x; 1.0858x over previous
#include <cuda_runtime.h>
#include <cuda_bf16.h>
#include <math.h>
#include <stdint.h>

// Problem constants
#define BB   16
#define NN1  1024
#define NN2  4096
#define CC1  256
#define CC2  128
#define CIN  384           // C1 + C2
#define HH   256           // H1 == H2
#define MM   (BB * NN2)    // 65536 rows through the MLP

// ---------------------------------------------------------------------------
// Scratch (device globals; no allocations allowed)
// ---------------------------------------------------------------------------
__device__ float g_f1t[(size_t)BB * NN1 * CC1];     // f1 transposed [B][N1][C1]
__device__ __align__(256) unsigned short g_Xh[(size_t)MM * CIN];  // X bf16 hi, row-major
__device__ __align__(256) unsigned short g_Xl[(size_t)MM * CIN];  // X bf16 lo
__device__ float g_Y1 [(size_t)HH * MM];            // layer1 pre-BN, COLUMN-major [c][m]
__device__ __align__(256) unsigned short g_Y1h[(size_t)MM * HH];  // act(Y1) bf16 hi, row-major
__device__ __align__(256) unsigned short g_Y1l[(size_t)MM * HH];  // act(Y1) bf16 lo
__device__ float g_Y2 [(size_t)HH * MM];            // layer2 pre-BN, COLUMN-major [c][m]
__device__ float g_sum[4 * HH];                     // [sum1 | sq1 | sum2 | sq2]
__device__ float g_nrm[4 * HH];                     // [sc1 | sh1 | sc2 | sh2]
__device__ __align__(256) unsigned short g_W1h[HH * CIN];
__device__ __align__(256) unsigned short g_W1l[HH * CIN];
__device__ __align__(256) unsigned short g_W2h[HH * HH];
__device__ __align__(256) unsigned short g_W2l[HH * HH];

// ---------------------------------------------------------------------------
// Helpers
// ---------------------------------------------------------------------------
__device__ __forceinline__ uint32_t smem_to_u32(const void* p) {
    uint32_t a;
    asm("{ .reg .u64 t; cvta.to.shared.u64 t, %1; cvt.u32.u64 %0, t; }" : "=r"(a) : "l"(p));
    return a;
}
__device__ __forceinline__ void bsplit(float x, unsigned short& h, unsigned short& l) {
    __nv_bfloat16 hb = __float2bfloat16_rn(x);
    float r = x - __bfloat162float(hb);
    __nv_bfloat16 lb = __float2bfloat16_rn(r);
    h = __bfloat16_as_ushort(hb);
    l = __bfloat16_as_ushort(lb);
}
__device__ __forceinline__ void cpa16(uint32_t d, const void* s) {
    asm volatile("cp.async.cg.shared.global [%0], [%1], 16;" :: "r"(d), "l"(s));
}
__device__ __forceinline__ void cp_commit() {
    asm volatile("cp.async.commit_group;");
}
template <int N>
__device__ __forceinline__ void cp_wait() {
    asm volatile("cp.async.wait_group %0;" :: "n"(N));
}
// mma.sync m16n8k16 bf16 -> f32 (HMMA path on sm_103; sm_80+ PTX)
__device__ __forceinline__ void mma16816(float* c, const uint32_t* a, const uint32_t* b) {
    asm volatile(
        "mma.sync.aligned.m16n8k16.row.col.f32.bf16.bf16.f32 "
        "{%0,%1,%2,%3}, {%4,%5,%6,%7}, {%8,%9}, {%0,%1,%2,%3};"
        : "+f"(c[0]), "+f"(c[1]), "+f"(c[2]), "+f"(c[3])
        : "r"(a[0]), "r"(a[1]), "r"(a[2]), "r"(a[3]), "r"(b[0]), "r"(b[1]));
}
// ldmatrix x4 (sm_75+): four 8x8 b16 tiles, per-lane row addresses
__device__ __forceinline__ void ldm_x4(uint32_t* r, uint32_t addr) {
    asm volatile("ldmatrix.sync.aligned.m8n8.x4.shared.b16 {%0,%1,%2,%3}, [%4];"
                 : "=r"(r[0]), "=r"(r[1]), "=r"(r[2]), "=r"(r[3]) : "r"(addr));
}

// ---------------------------------------------------------------------------
// Zero BN stat accumulators (re-zeroed every replay)
// ---------------------------------------------------------------------------
__global__ void zero_stats_kernel() {
    for (int i = threadIdx.x; i < 4 * HH; i += blockDim.x) g_sum[i] = 0.f;
}

// ---------------------------------------------------------------------------
// Split W (fp32) -> bf16 hi/lo globals (tiny, once per launch)
// ---------------------------------------------------------------------------
__global__ void split_w_kernel(const float* __restrict__ W,
                               unsigned short* __restrict__ H,
                               unsigned short* __restrict__ L, int n) {
    const int i = blockIdx.x * 256 + threadIdx.x;
    if (i < n) {
        unsigned short h, l;
        bsplit(W[i], h, l);
        H[i] = h; L[i] = l;
    }
}

// ---------------------------------------------------------------------------
// Transpose features1 [B][C1][N1] -> g_f1t [B][N1][C1]  (fp32, for gather)
// ---------------------------------------------------------------------------
__global__ __launch_bounds__(256) void transpose_f1_kernel(const float* __restrict__ f1) {
    __shared__ float t[32][33];
    const int b = blockIdx.z, n0 = blockIdx.x * 32, c0 = blockIdx.y * 32;
    const int tx = threadIdx.x, ty = threadIdx.y;
    const float* src = f1 + (size_t)b * CC1 * NN1;
#pragma unroll
    for (int i = 0; i < 4; i++)
        t[ty + 8 * i][tx] = src[(size_t)(c0 + ty + 8 * i) * NN1 + n0 + tx];
    __syncthreads();
    float* dst = g_f1t + (size_t)b * NN1 * CC1;
#pragma unroll
    for (int i = 0; i < 4; i++)
        dst[(size_t)(n0 + ty + 8 * i) * CC1 + c0 + tx] = t[tx][ty + 8 * i];
}

// ---------------------------------------------------------------------------
// Transpose features2 [B][C2][N2] into X[:, C1:CIN], written bf16-split
// ---------------------------------------------------------------------------
__global__ __launch_bounds__(256) void concat_f2_kernel(const float* __restrict__ f2) {
    __shared__ float t[32][33];
    const int b = blockIdx.z, n0 = blockIdx.x * 32, c0 = blockIdx.y * 32;
    const int tx = threadIdx.x, ty = threadIdx.y;
    const float* src = f2 + (size_t)b * CC2 * NN2;
#pragma unroll
    for (int i = 0; i < 4; i++)
        t[ty + 8 * i][tx] = src[(size_t)(c0 + ty + 8 * i) * NN2 + n0 + tx];
    __syncthreads();
#pragma unroll
    for (int i = 0; i < 4; i++) {
        const size_t m = (size_t)b * NN2 + n0 + ty + 8 * i;
        unsigned short h, l;
        bsplit(t[tx][ty + 8 * i], h, l);
        g_Xh[m * CIN + CC1 + c0 + tx] = h;
        g_Xl[m * CIN + CC1 + c0 + tx] = l;
    }
}

// ---------------------------------------------------------------------------
// 3-NN + inverse-distance interpolation -> X[:, 0:C1] (bf16-split)
// 512 blocks (128 queries/block), 2 threads per query each scanning 512 refs,
// then a tie-stable 3-way merge (half 0 preferred on ties = lower index,
// matching top_k's stable order). Distance arithmetic bit-exact vs reference.
// ---------------------------------------------------------------------------
__global__ __launch_bounds__(256) void knn_interp_kernel(const float* __restrict__ p1,
                                                         const float* __restrict__ p2) {
    __shared__ float4 sp[NN1];
    __shared__ float  s_bd[2 * 128 * 3];
    __shared__ int    s_bi[2 * 128 * 3];
    __shared__ float  s_w[128 * 3];
    __shared__ int    s_idx[128 * 3];

    const int b    = blockIdx.y;
    const int tid  = threadIdx.x;
    const int ql   = tid & 127;
    const int half = tid >> 7;
    const int q0   = blockIdx.x * 128;

    const float* p1b = p1 + (size_t)b * 3 * NN1;
    for (int i = tid; i < NN1; i += 256) {
        float x = p1b[i], y = p1b[NN1 + i], z = p1b[2 * NN1 + i];
        float n = __fadd_rn(__fadd_rn(__fmul_rn(x, x), __fmul_rn(y, y)), __fmul_rn(z, z));
        sp[i] = make_float4(x, y, z, n);
    }
    __syncthreads();

    const int q = q0 + ql;
    const float* p2b = p2 + (size_t)b * 3 * NN2;
    const float qx = p2b[q], qy = p2b[NN2 + q], qz = p2b[2 * NN2 + q];
    const float qn = __fadd_rn(__fadd_rn(__fmul_rn(qx, qx), __fmul_rn(qy, qy)),
                               __fmul_rn(qz, qz));

    float d0 = 1e30f, d1 = 1e30f, d2 = 1e30f;
    int   i0 = 0, i1 = 0, i2 = 0;
    const int nbeg = half * 512;
#pragma unroll 4
    for (int n = nbeg; n < nbeg + 512; n++) {
        const float4 f = sp[n];
        const float dot = __fmaf_rn(qz, f.z, __fmaf_rn(qy, f.y, __fmul_rn(qx, f.x)));
        const float d = __fsub_rn(__fadd_rn(qn, f.w), __fadd_rn(dot, dot));
        if (d < d2) {
            if (d < d1) {
                d2 = d1; i2 = i1;
                if (d < d0) { d1 = d0; i1 = i0; d0 = d; i0 = n; }
                else        { d1 = d;  i1 = n; }
            } else { d2 = d; i2 = n; }
        }
    }
    const int base = (half * 128 + ql) * 3;
    s_bd[base + 0] = d0; s_bd[base + 1] = d1; s_bd[base + 2] = d2;
    s_bi[base + 0] = i0; s_bi[base + 1] = i1; s_bi[base + 2] = i2;
    __syncthreads();

    if (tid < 128) {
        const float* da = &s_bd[tid * 3];
        const int*   ia = &s_bi[tid * 3];
        const float* db = &s_bd[(128 + tid) * 3];
        const int*   ib = &s_bi[(128 + tid) * 3];
        float dm[3]; int im[3];
        int ai = 0, bi = 0;
#pragma unroll
        for (int s = 0; s < 3; s++) {
            const float dA = da[ai], dB = db[bi];
            if (dB < dA) { dm[s] = dB; im[s] = ib[bi]; bi++; }
            else         { dm[s] = dA; im[s] = ia[ai]; ai++; }
        }
        const float v0 = __fdiv_rn(1.f, fmaxf(dm[0], 1e-10f));
        const float v1 = __fdiv_rn(1.f, fmaxf(dm[1], 1e-10f));
        const float v2 = __fdiv_rn(1.f, fmaxf(dm[2], 1e-10f));
        const float s  = __fadd_rn(__fadd_rn(v0, v1), v2);
        s_idx[tid * 3 + 0] = im[0]; s_idx[tid * 3 + 1] = im[1]; s_idx[tid * 3 + 2] = im[2];
        s_w[tid * 3 + 0] = __fdiv_rn(v0, s);
        s_w[tid * 3 + 1] = __fdiv_rn(v1, s);
        s_w[tid * 3 + 2] = __fdiv_rn(v2, s);
    }
    __syncthreads();

    const float* f1t = g_f1t + (size_t)b * NN1 * CC1;
    const size_t mrow0 = (size_t)b * NN2 + q0;
    const int c = tid;
    for (int qq = 0; qq < 128; qq++) {
        const int   a0 = s_idx[qq * 3 + 0], a1 = s_idx[qq * 3 + 1], a2 = s_idx[qq * 3 + 2];
        const float w0 = s_w[qq * 3 + 0],  w1 = s_w[qq * 3 + 1],  w2 = s_w[qq * 3 + 2];
        const float t0 = __fmul_rn(f1t[(size_t)a0 * CC1 + c], w0);
        const float t1 = __fmul_rn(f1t[(size_t)a1 * CC1 + c], w1);
        const float t2 = __fmul_rn(f1t[(size_t)a2 * CC1 + c], w2);
        const float v  = __fadd_rn(__fadd_rn(t0, t1), t2);
        unsigned short h, l;
        bsplit(v, h, l);
        g_Xh[(mrow0 + qq) * CIN + c] = h;
        g_Xl[(mrow0 + qq) * CIN + c] = l;
    }
}

// ---------------------------------------------------------------------------
// mma.sync bf16-split GEMM: Y[c][m] = A[m,:] . W[c,:] + bias[c]
// A and W pre-split (bf16 hi/lo) row-major. cp.async double-buffered
// (2 stages x 4 tiles). ldmatrix.x4 fragment loads (12 per k16-step vs 48
// LDS.32). 3-term compensation: ah*bh + al*bh + ah*bl (fp32 accumulators).
// Block = 128 rows x 128 cols, 8 warps (2M x 4N), 64x32 per warp.
// Grid (2, 512): n-tile fastest so A panels are L2-resident on reuse.
// Epilogue: stage tile in smem as F[n][132] -> warp-per-column float4
// stores (fully coalesced) with BN stats via shfl in the same pass.
// ---------------------------------------------------------------------------
#define ASTRIDE 40                    // u16 stride per row (32 k + 8 pad)
#define TILE_U16 (128 * ASTRIDE)      // 5120 u16 = 10240 B
#define STAGE_U16 (4 * TILE_U16)      // 20480 u16 = 40960 B
#define GEMM_SMEM (2 * STAGE_U16 * 2 + 3 * 128 * 4)   // 83456 B

template <int K>
__global__ __launch_bounds__(256)
void gemm_mma_kernel(const unsigned short* __restrict__ GAh,
                     const unsigned short* __restrict__ GAl,
                     const unsigned short* __restrict__ GWh,
                     const unsigned short* __restrict__ GWl,
                     const float* __restrict__ bias,
                     float* __restrict__ Y,
                     float* __restrict__ osum,
                     float* __restrict__ osq) {
    extern __shared__ char smem[];
    const uint32_t sb = smem_to_u32(smem);
    float* s_bias = (float*)(smem + 2 * STAGE_U16 * 2);
    float* s_sum  = s_bias + 128;
    float* s_sq   = s_sum + 128;

    const int tid  = threadIdx.x;
    const int lane = tid & 31;
    const int wid  = tid >> 5;
    const int n0   = blockIdx.x * 128;
    const int m0   = blockIdx.y * 128;
    const int m_base = (wid & 1) * 64;
    const int n_base = (wid >> 1) * 32;

    if (tid < 128) s_bias[tid] = bias[n0 + tid];

    float acc[4][4][4];
#pragma unroll
    for (int a = 0; a < 4; a++)
#pragma unroll
        for (int b = 0; b < 4; b++)
#pragma unroll
            for (int c = 0; c < 4; c++) acc[a][b][c] = 0.f;

    // cp.async mapping: each thread copies 2x16B per tile (rows tid>>1)
    const int crow = tid >> 1;
    const int ckoff = (tid & 1) * 16;                    // u16 offset within 32-k chunk

    auto issue = [&](int ch, int st) {
        const int kb = ch * 32 + ckoff;
        const unsigned short* a_h = GAh + (size_t)(m0 + crow) * K + kb;
        const unsigned short* a_l = GAl + (size_t)(m0 + crow) * K + kb;
        const unsigned short* w_h = GWh + (size_t)(n0 + crow) * K + kb;
        const unsigned short* w_l = GWl + (size_t)(n0 + crow) * K + kb;
        const uint32_t so = sb + (uint32_t)(st * STAGE_U16 + crow * ASTRIDE + ckoff) * 2u;
        cpa16(so, a_h);                          cpa16(so + 16, a_h + 8);
        cpa16(so + TILE_U16 * 2, a_l);           cpa16(so + TILE_U16 * 2 + 16, a_l + 8);
        cpa16(so + TILE_U16 * 4, w_h);           cpa16(so + TILE_U16 * 4 + 16, w_h + 8);
        cpa16(so + TILE_U16 * 6, w_l);           cpa16(so + TILE_U16 * 6 + 16, w_l + 8);
        cp_commit();
    };

    // ldmatrix per-lane offsets (u16 units within a tile)
    const uint32_t a_loff = (uint32_t)(((lane & 7) + ((lane >> 3) & 1) * 8) * ASTRIDE
                                       + (lane >> 4) * 8);
    const uint32_t b_loff = (uint32_t)(((lane & 7) + (lane >> 4) * 8) * ASTRIDE
                                       + ((lane >> 3) & 1) * 8);

    constexpr int NCH = K / 32;
    issue(0, 0);
    int buf = 0;
    for (int ch = 0; ch < NCH; ch++) {
        if (ch + 1 < NCH) { issue(ch + 1, buf ^ 1); cp_wait<1>(); }
        else              { cp_wait<0>(); }
        __syncthreads();

        const uint32_t sAh = sb + (uint32_t)(buf * STAGE_U16) * 2u;
        const uint32_t sAl = sAh + TILE_U16 * 2u;
        const uint32_t sWh = sAl + TILE_U16 * 2u;
        const uint32_t sWl = sWh + TILE_U16 * 2u;

#pragma unroll
        for (int kk = 0; kk < 32; kk += 16) {
            uint32_t afh[4][4], afl[4][4];
#pragma unroll
            for (int mt = 0; mt < 4; mt++) {
                const uint32_t off = ((uint32_t)((m_base + mt * 16) * ASTRIDE + kk)
                                      + a_loff) * 2u;
                ldm_x4(afh[mt], sAh + off);
                ldm_x4(afl[mt], sAl + off);
            }
            uint32_t bfh[4][2], bfl[4][2];
#pragma unroll
            for (int np = 0; np < 2; np++) {
                const uint32_t off = ((uint32_t)((n_base + np * 16) * ASTRIDE + kk)
                                      + b_loff) * 2u;
                uint32_t th[4], tl[4];
                ldm_x4(th, sWh + off);
                ldm_x4(tl, sWl + off);
                bfh[2 * np][0] = th[0]; bfh[2 * np][1] = th[1];
                bfh[2 * np + 1][0] = th[2]; bfh[2 * np + 1][1] = th[3];
                bfl[2 * np][0] = tl[0]; bfl[2 * np][1] = tl[1];
                bfl[2 * np + 1][0] = tl[2]; bfl[2 * np + 1][1] = tl[3];
            }
#pragma unroll
            for (int mt = 0; mt < 4; mt++)
#pragma unroll
                for (int nt = 0; nt < 4; nt++) {
                    mma16816(acc[mt][nt], afh[mt], bfh[nt]);
                    mma16816(acc[mt][nt], afl[mt], bfh[nt]);
                    mma16816(acc[mt][nt], afh[mt], bfl[nt]);
                }
        }
        __syncthreads();
        buf ^= 1;
    }

    // ---- Epilogue: stage into F[n][132], coalesced col stores + BN stats ----
    float* F = (float*)smem;            // 128*132*4 = 67584 B, fits in stage area
#pragma unroll
    for (int nt = 0; nt < 4; nt++) {
        const int n = n_base + nt * 8 + 2 * (lane & 3);
        const float b0 = s_bias[n], b1 = s_bias[n + 1];
#pragma unroll
        for (int mt = 0; mt < 4; mt++) {
            const int r = m_base + mt * 16 + (lane >> 2);
            F[n * 132 + r]           = acc[mt][nt][0] + b0;
            F[(n + 1) * 132 + r]     = acc[mt][nt][1] + b1;
            F[n * 132 + r + 8]       = acc[mt][nt][2] + b0;
            F[(n + 1) * 132 + r + 8] = acc[mt][nt][3] + b1;
        }
    }
    __syncthreads();
#pragma unroll 1
    for (int c = wid; c < 128; c += 8) {
        float4 v = *(float4*)&F[c * 132 + lane * 4];
        float s = v.x + v.y + v.z + v.w;
        float q = v.x * v.x + v.y * v.y + v.z * v.z + v.w * v.w;
#pragma unroll
        for (int off = 16; off >= 1; off >>= 1) {
            s += __shfl_xor_sync(0xFFFFFFFFu, s, off);
            q += __shfl_xor_sync(0xFFFFFFFFu, q, off);
        }
        *(float4*)&Y[(size_t)(n0 + c) * MM + m0 + lane * 4] = v;
        if (lane == 0) { s_sum[c] = s; s_sq[c] = q; }
    }
    __syncthreads();
    if (tid < 128) {
        atomicAdd(&osum[n0 + tid], s_sum[tid]);
        atomicAdd(&osq[n0 + tid], s_sq[tid]);
    }
}

// ---------------------------------------------------------------------------
// Finalize BN stats -> per-channel (scale, shift)
// ---------------------------------------------------------------------------
__global__ void stats_final_kernel(const float* __restrict__ gamma,
                                   const float* __restrict__ beta,
                                   int layer) {
    const int c = threadIdx.x;
    if (c >= HH) return;
    const float invM = 1.f / (float)MM;
    const float s = g_sum[layer * 512 + c];
    const float q = g_sum[layer * 512 + 256 + c];
    const float mean = s * invM;
    const float var = fmaxf(q * invM - mean * mean, 0.f);
    const float rstd = rsqrtf(var + 1e-3f);
    const float scale = gamma[c] * rstd;
    g_nrm[layer * 512 + c] = scale;
    g_nrm[layer * 512 + 256 + c] = beta[c] - mean * scale;
}

// ---------------------------------------------------------------------------
// prep2: Y1 col-major fp32 -> BN+ReLU -> bf16 split, transposed to
// row-major [m][HH]. grid (MM/32, HH/32), block (32, 8); both sides coalesced.
// ---------------------------------------------------------------------------
__global__ __launch_bounds__(256) void prep2_kernel() {
    __shared__ float t[32][33];
    const int m0 = blockIdx.x * 32, c0 = blockIdx.y * 32;
    const int tx = threadIdx.x, ty = threadIdx.y;
#pragma unroll
    for (int i = 0; i < 4; i++) {
        const int cc = c0 + ty + 8 * i;
        float v = g_Y1[(size_t)cc * MM + m0 + tx];
        t[ty + 8 * i][tx] = fmaxf(0.f, fmaf(v, g_nrm[cc], g_nrm[256 + cc]));
    }
    __syncthreads();
#pragma unroll
    for (int i = 0; i < 4; i++) {
        const size_t m = (size_t)(m0 + ty + 8 * i);
        unsigned short h, l;
        bsplit(t[tx][ty + 8 * i], h, l);
        g_Y1h[m * HH + c0 + tx] = h;
        g_Y1l[m * HH + c0 + tx] = l;
    }
}

// ---------------------------------------------------------------------------
// Final: layer-2 BN + ReLU, Y2 col-major [c][b*4096+n] -> out[b][c][n]
// float4 both sides; grid (MM/1024, HH).
// ---------------------------------------------------------------------------
__global__ __launch_bounds__(256) void out_bn_kernel(float* __restrict__ out) {
    const int m = (blockIdx.x * 256 + threadIdx.x) * 4;
    const int c = blockIdx.y;
    float4 v = *(const float4*)&g_Y2[(size_t)c * MM + m];
    const float sc = g_nrm[512 + c], sh = g_nrm[768 + c];
    v.x = fmaxf(0.f, fmaf(v.x, sc, sh));
    v.y = fmaxf(0.f, fmaf(v.y, sc, sh));
    v.z = fmaxf(0.f, fmaf(v.z, sc, sh));
    v.w = fmaxf(0.f, fmaf(v.w, sc, sh));
    const int b = m >> 12;
    const int n = m & 4095;
    *(float4*)&out[(size_t)b * HH * NN2 + (size_t)c * NN2 + n] = v;
}

// ---------------------------------------------------------------------------
// Launch
// ---------------------------------------------------------------------------
extern "C" void kernel_launch(void* const* d_in, const int* in_sizes, int n_in,
                              void* d_out, int out_size) {
    (void)in_sizes; (void)n_in; (void)out_size;
    const float* points1   = (const float*)d_in[0];
    const float* points2   = (const float*)d_in[1];
    const float* features1 = (const float*)d_in[2];
    const float* features2 = (const float*)d_in[3];
    const float* W1  = (const float*)d_in[4];
    const float* b1  = (const float*)d_in[5];
    const float* gm1 = (const float*)d_in[6];
    const float* be1 = (const float*)d_in[7];
    const float* W2  = (const float*)d_in[8];
    const float* b2  = (const float*)d_in[9];
    const float* gm2 = (const float*)d_in[10];
    const float* be2 = (const float*)d_in[11];
    float* out = (float*)d_out;

    unsigned short *w1h, *w1l, *w2h, *w2l, *xh, *xl, *y1h, *y1l;
    float *y1, *y2, *gsum;
    cudaGetSymbolAddress((void**)&w1h, g_W1h);
    cudaGetSymbolAddress((void**)&w1l, g_W1l);
    cudaGetSymbolAddress((void**)&w2h, g_W2h);
    cudaGetSymbolAddress((void**)&w2l, g_W2l);
    cudaGetSymbolAddress((void**)&xh,  g_Xh);
    cudaGetSymbolAddress((void**)&xl,  g_Xl);
    cudaGetSymbolAddress((void**)&y1h, g_Y1h);
    cudaGetSymbolAddress((void**)&y1l, g_Y1l);
    cudaGetSymbolAddress((void**)&y1,  g_Y1);
    cudaGetSymbolAddress((void**)&y2,  g_Y2);
    cudaGetSymbolAddress((void**)&gsum, g_sum);

    cudaFuncSetAttribute(gemm_mma_kernel<CIN>,
                         cudaFuncAttributeMaxDynamicSharedMemorySize, GEMM_SMEM);
    cudaFuncSetAttribute(gemm_mma_kernel<HH>,
                         cudaFuncAttributeMaxDynamicSharedMemorySize, GEMM_SMEM);

    zero_stats_kernel<<<1, 256>>>();
    split_w_kernel<<<(HH * CIN + 255) / 256, 256>>>(W1, w1h, w1l, HH * CIN);
    split_w_kernel<<<(HH * HH + 255) / 256, 256>>>(W2, w2h, w2l, HH * HH);
    transpose_f1_kernel<<<dim3(NN1 / 32, CC1 / 32, BB), dim3(32, 8)>>>(features1);
    concat_f2_kernel<<<dim3(NN2 / 32, CC2 / 32, BB), dim3(32, 8)>>>(features2);
    knn_interp_kernel<<<dim3(NN2 / 128, BB), 256>>>(points1, points2);

    gemm_mma_kernel<CIN><<<dim3(2, MM / 128), 256, GEMM_SMEM>>>(
        xh, xl, w1h, w1l, b1, y1, gsum, gsum + 256);
    stats_final_kernel<<<1, 256>>>(gm1, be1, 0);
    prep2_kernel<<<dim3(MM / 32, HH / 32), dim3(32, 8)>>>();

    gemm_mma_kernel<HH><<<dim3(2, MM / 128), 256, GEMM_SMEM>>>(
        y1h, y1l, w2h, w2l, b2, y2, gsum + 512, gsum + 768);
    stats_final_kernel<<<1, 256>>>(gm2, be2, 1);

    out_bn_kernel<<<dim3(MM / 1024, HH), 256>>>(out);
}